// round 10
// baseline (speedup 1.0000x reference)
#include <cuda_runtime.h>

#define BB    64
#define TTT   512
#define IN    512
#define HH    1024
#define G4    4096
#define NSTEP 1024
#define KC    32
#define NCTA  128

// 512 MB scratch for G[t][b][4096] = x_t @ Ww^T + (bw + bu)
__device__ float g_G[(size_t)TTT * BB * G4];

// grid-barrier state (zero-initialized; g_cnt returns to 0 every barrier,
// g_gen is compared relatively so monotonic growth across replays is fine)
__device__ unsigned g_cnt;
__device__ volatile unsigned g_gen;

__device__ __forceinline__ unsigned long long fma2(unsigned long long a,
                                                   unsigned long long b,
                                                   unsigned long long c) {
    unsigned long long d;
    asm("fma.rn.f32x2 %0, %1, %2, %3;" : "=l"(d) : "l"(a), "l"(b), "l"(c));
    return d;
}
__device__ __forceinline__ unsigned long long dup2(float v) {
    unsigned int u = __float_as_uint(v);
    return ((unsigned long long)u << 32) | (unsigned long long)u;
}
__device__ __forceinline__ float sigm(float x) { return 1.f / (1.f + __expf(-x)); }

__device__ __forceinline__ void grid_barrier(int tid) {
    __syncthreads();
    if (tid == 0) {
        __threadfence();                       // publish this CTA's h/c stores
        unsigned gen = g_gen;
        if (atomicAdd(&g_cnt, 1u) == NCTA - 1) {
            g_cnt = 0;
            __threadfence();                   // order cnt reset before release
            g_gen = gen + 1;                   // release
        } else {
            while (g_gen == gen) { __nanosleep(64); }
        }
        __threadfence();                       // acquire
    }
    __syncthreads();
}

// ---------------------------------------------------------------------------
// Persistent scan kernel: 128 CTAs (1/SM), loops s = 0..1023.
// Per step: gates = G[t] + h_prev @ Uw^T (CTA tile 64x32, K=1024, KC=32
// double-buffered, thread tile 2Mx4N via fma.rn.f32x2), then fused LSTM
// pointwise update writing h/c straight into d_out. Grid barrier between steps.
// ---------------------------------------------------------------------------
__global__ __launch_bounds__(256) void lstm_scan(const float* __restrict__ Uw,
                                                 float* __restrict__ out) {
    __shared__ __align__(16) unsigned long long sh_h[2 * KC * 66]; // dup'd h, padded
    __shared__ __align__(16) float sh_u[2 * KC * 36];              // Uw slice, padded
    float* gb = sh_u;  // gate-exchange buffer (64 x 34 floats) aliases sh_u

    const int tid  = threadIdx.x;
    const int lane = tid & 31;        // = k within chunk for staging
    const int w    = tid >> 5;        // warp id (8 warps)
    const int g    = blockIdx.x;      // 0..127
    const int j0   = g * 8;
    const int mg   = tid >> 3, ng = tid & 7;
    const int m0   = mg * 2,  n0 = ng * 4;

    for (int s = 0; s < NSTEP; s++) {
        unsigned long long a00 = 0ull, a01 = 0ull, a10 = 0ull, a11 = 0ull;

        if (s > 0) {
            const float* hprev = out + (size_t)(s - 1) * (BB * HH);

            float hr[8], ur[4];
            // prologue: chunk 0 -> regs -> smem buf 0
#pragma unroll
            for (int i = 0; i < 8; i++) hr[i] = hprev[(w + i * 8) * HH + lane];
#pragma unroll
            for (int i = 0; i < 4; i++) {
                int c = w * 4 + i;
                int n = (c >> 3) * HH + j0 + (c & 7);
                ur[i] = Uw[(size_t)n * HH + lane];
            }
#pragma unroll
            for (int i = 0; i < 8; i++) sh_h[lane * 66 + (w + i * 8)] = dup2(hr[i]);
#pragma unroll
            for (int i = 0; i < 4; i++) sh_u[lane * 36 + w * 4 + i] = ur[i];

            int buf = 0;
            const int NCH = HH / KC;  // 32
            for (int ch = 0; ch < NCH; ch++) {
                __syncthreads();  // buf[buf] ready
                if (ch + 1 < NCH) {
                    int kc = (ch + 1) * KC;
#pragma unroll
                    for (int i = 0; i < 8; i++)
                        hr[i] = hprev[(w + i * 8) * HH + kc + lane];
#pragma unroll
                    for (int i = 0; i < 4; i++) {
                        int c = w * 4 + i;
                        int n = (c >> 3) * HH + j0 + (c & 7);
                        ur[i] = Uw[(size_t)n * HH + kc + lane];
                    }
                }
                const unsigned long long* hb = sh_h + buf * (KC * 66) + m0;
                const float* ub = sh_u + buf * (KC * 36) + n0;
#pragma unroll 8
                for (int kk = 0; kk < KC; kk++) {
                    ulonglong2 hp = *(const ulonglong2*)(hb + kk * 66);
                    ulonglong2 up = *(const ulonglong2*)(ub + kk * 36);
                    a00 = fma2(hp.x, up.x, a00);
                    a01 = fma2(hp.x, up.y, a01);
                    a10 = fma2(hp.y, up.x, a10);
                    a11 = fma2(hp.y, up.y, a11);
                }
                if (ch + 1 < NCH) {
                    int nb = buf ^ 1;
#pragma unroll
                    for (int i = 0; i < 8; i++)
                        sh_h[nb * (KC * 66) + lane * 66 + (w + i * 8)] = dup2(hr[i]);
#pragma unroll
                    for (int i = 0; i < 4; i++)
                        sh_u[nb * (KC * 36) + lane * 36 + w * 4 + i] = ur[i];
                }
                buf ^= 1;
            }
        }
        __syncthreads();  // everyone done reading sh_u before gbuf reuse

        // gate exchange: acc -> smem (rows m0,m0+1; cols n0..n0+3)
        *(unsigned long long*)&gb[m0 * 34 + n0]           = a00;
        *(unsigned long long*)&gb[m0 * 34 + n0 + 2]       = a01;
        *(unsigned long long*)&gb[(m0 + 1) * 34 + n0]     = a10;
        *(unsigned long long*)&gb[(m0 + 1) * 34 + n0 + 2] = a11;
        __syncthreads();

        // fused pointwise LSTM update: 512 (b, unit) pairs, 2 per thread
        const int t = s >> 1;
        const size_t gbase = (size_t)(t * BB) * G4;
#pragma unroll
        for (int e = 0; e < 2; e++) {
            int p = tid * 2 + e;
            int b = p >> 3, uu = p & 7;
            size_t gg_idx = gbase + (size_t)b * G4 + j0 + uu;
            float gi = gb[b * 34 + uu]      + g_G[gg_idx];
            float gf = gb[b * 34 + 8 + uu]  + g_G[gg_idx + HH];
            float gG = gb[b * 34 + 16 + uu] + g_G[gg_idx + 2 * HH];
            float go = gb[b * 34 + 24 + uu] + g_G[gg_idx + 3 * HH];

            size_t oidx = (size_t)s * (BB * HH) + (size_t)b * HH + j0 + uu;
            float cp = 0.f;
            if (s > 0) cp = out[(size_t)NSTEP * (BB * HH) + oidx - (BB * HH)];
            float cn = cp * sigm(gf) + sigm(gi) * tanhf(gG);
            float hn = sigm(go) * tanhf(cn);
            out[oidx] = hn;
            out[(size_t)NSTEP * (BB * HH) + oidx] = cn;
        }

        grid_barrier(tid);  // h/c of step s visible chip-wide before step s+1
    }
}

// ---------------------------------------------------------------------------
// Precompute kernel: G[t][b][n] = bias[n] + sum_k x[b][t][k] * Ww[n][k]
// Grid: (128 n-groups of 32, 512 t). Same micro-kernel, K = 512.
// ---------------------------------------------------------------------------
__global__ __launch_bounds__(256) void lstm_pre(const float* __restrict__ x,
                                                const float* __restrict__ Ww,
                                                const float* __restrict__ bw,
                                                const float* __restrict__ bu) {
    __shared__ __align__(16) unsigned long long sh_h[2 * KC * 66];
    __shared__ __align__(16) float sh_u[2 * KC * 36];
    float* gb = sh_u;

    const int tid  = threadIdx.x;
    const int lane = tid & 31;
    const int w    = tid >> 5;
    const int n0g  = blockIdx.x * 32;
    const int t    = blockIdx.y;
    const int mg   = tid >> 3, ng = tid & 7;
    const int m0   = mg * 2,  n0 = ng * 4;

    unsigned long long a00 = 0ull, a01 = 0ull, a10 = 0ull, a11 = 0ull;

    float hr[8], ur[4];
#pragma unroll
    for (int i = 0; i < 8; i++)
        hr[i] = x[((size_t)(w + i * 8) * TTT + t) * IN + lane];
#pragma unroll
    for (int i = 0; i < 4; i++)
        ur[i] = Ww[(size_t)(n0g + w * 4 + i) * IN + lane];
#pragma unroll
    for (int i = 0; i < 8; i++) sh_h[lane * 66 + (w + i * 8)] = dup2(hr[i]);
#pragma unroll
    for (int i = 0; i < 4; i++) sh_u[lane * 36 + w * 4 + i] = ur[i];

    int buf = 0;
    const int NCH = IN / KC;  // 16
    for (int ch = 0; ch < NCH; ch++) {
        __syncthreads();
        if (ch + 1 < NCH) {
            int kc = (ch + 1) * KC;
#pragma unroll
            for (int i = 0; i < 8; i++)
                hr[i] = x[((size_t)(w + i * 8) * TTT + t) * IN + kc + lane];
#pragma unroll
            for (int i = 0; i < 4; i++)
                ur[i] = Ww[(size_t)(n0g + w * 4 + i) * IN + kc + lane];
        }
        const unsigned long long* hb = sh_h + buf * (KC * 66) + m0;
        const float* ub = sh_u + buf * (KC * 36) + n0;
#pragma unroll 8
        for (int kk = 0; kk < KC; kk++) {
            ulonglong2 hp = *(const ulonglong2*)(hb + kk * 66);
            ulonglong2 up = *(const ulonglong2*)(ub + kk * 36);
            a00 = fma2(hp.x, up.x, a00);
            a01 = fma2(hp.x, up.y, a01);
            a10 = fma2(hp.y, up.x, a10);
            a11 = fma2(hp.y, up.y, a11);
        }
        if (ch + 1 < NCH) {
            int nb = buf ^ 1;
#pragma unroll
            for (int i = 0; i < 8; i++)
                sh_h[nb * (KC * 66) + lane * 66 + (w + i * 8)] = dup2(hr[i]);
#pragma unroll
            for (int i = 0; i < 4; i++)
                sh_u[nb * (KC * 36) + lane * 36 + w * 4 + i] = ur[i];
        }
        buf ^= 1;
    }
    __syncthreads();

    *(unsigned long long*)&gb[m0 * 34 + n0]           = a00;
    *(unsigned long long*)&gb[m0 * 34 + n0 + 2]       = a01;
    *(unsigned long long*)&gb[(m0 + 1) * 34 + n0]     = a10;
    *(unsigned long long*)&gb[(m0 + 1) * 34 + n0 + 2] = a11;
    __syncthreads();

    // coalesced flush + bias
#pragma unroll
    for (int i = 0; i < 8; i++) {
        int f = i * 256 + tid;
        int b = f >> 5, c = f & 31;
        int n = n0g + c;
        g_G[((size_t)t * BB + b) * G4 + n] = gb[b * 34 + c] + bw[n] + bu[n];
    }
}

extern "C" void kernel_launch(void* const* d_in, const int* in_sizes, int n_in,
                              void* d_out, int out_size) {
    const float* x  = (const float*)d_in[0];
    const float* Ww = (const float*)d_in[1];
    const float* bw = (const float*)d_in[2];
    const float* Uw = (const float*)d_in[3];
    const float* bu = (const float*)d_in[4];
    float* out = (float*)d_out;

    (void)in_sizes; (void)n_in; (void)out_size;

    lstm_pre<<<dim3(128, 512), 256>>>(x, Ww, bw, bu);
    lstm_scan<<<NCTA, 256>>>(Uw, out);
}

// round 11
// speedup vs baseline: 1.5843x; 1.5843x over previous
#include <cuda_runtime.h>

#define BB    64
#define TTT   512
#define IN    512
#define HH    1024
#define G4    4096
#define NSTEP 1024
#define KC    32
#define NCTA  128

// 512 MB scratch for G[t][b][4096] = x_t @ Ww^T + (bw + bu)
__device__ float g_G[(size_t)TTT * BB * G4];

// grid-barrier state (zero-initialized; g_cnt returns to 0 every barrier,
// g_gen is compared relatively so monotonic growth across replays is fine)
__device__ unsigned g_cnt;
__device__ volatile unsigned g_gen;

__device__ __forceinline__ unsigned long long fma2(unsigned long long a,
                                                   unsigned long long b,
                                                   unsigned long long c) {
    unsigned long long d;
    asm("fma.rn.f32x2 %0, %1, %2, %3;" : "=l"(d) : "l"(a), "l"(b), "l"(c));
    return d;
}
__device__ __forceinline__ unsigned long long dup2(float v) {
    unsigned int u = __float_as_uint(v);
    unsigned long long d;
    asm("mov.b64 %0, {%1, %1};" : "=l"(d) : "r"(u));
    return d;
}
__device__ __forceinline__ float sigm(float x) { return 1.f / (1.f + __expf(-x)); }

__device__ __forceinline__ void grid_barrier(int tid) {
    __syncthreads();
    if (tid == 0) {
        __threadfence();                       // publish this CTA's h/c stores
        unsigned gen = g_gen;
        if (atomicAdd(&g_cnt, 1u) == NCTA - 1) {
            g_cnt = 0;
            __threadfence();                   // order cnt reset before release
            g_gen = gen + 1;                   // release
        } else {
            while (g_gen == gen) { }           // pure spin (L2 polls, tid0 only)
        }
        __threadfence();                       // acquire
    }
    __syncthreads();
}

// ---------------------------------------------------------------------------
// Persistent scan kernel: 128 CTAs (1/SM), loops s = 0..1023.
// Per step: gates = G[t] + h_prev @ Uw^T (CTA tile 64x32, K=1024, KC=32
// double-buffered, thread tile 2Mx4N via fma.rn.f32x2), fused LSTM pointwise.
// Staging uses full-width STS.128 only: with row strides 132/36 floats
// (== 4 mod 32), a warp's 32x16B stores hit bank-groups (lane+c) mod 8 ->
// exactly 4 wavefronts per STS.128 (bandwidth floor, conflict-free).
// ---------------------------------------------------------------------------
__global__ __launch_bounds__(256, 1) void lstm_scan(const float* __restrict__ Uw,
                                                    float* __restrict__ out) {
    __shared__ __align__(16) unsigned long long sh_h[2 * KC * 66]; // dup'd h
    __shared__ __align__(16) float sh_u[2 * KC * 36];              // Uw slice
    float* gb = sh_u;  // gate-exchange buffer (64 x 34 floats) aliases sh_u

    const int tid  = threadIdx.x;
    const int lane = tid & 31;        // = k within chunk for staging
    const int w    = tid >> 5;        // warp id (8 warps)
    const int g    = blockIdx.x;      // 0..127
    const int j0   = g * 8;
    const int mg   = tid >> 3, ng = tid & 7;
    const int m0   = mg * 2,  n0 = ng * 4;

    // precomputed staging indices
    const int hst = lane * 66 + 8 * w;   // u64 index, 16B-aligned (even)
    const int ust = lane * 36 + 4 * w;   // float index, 16B-aligned

    for (int s = 0; s < NSTEP; s++) {
        unsigned long long a00 = 0ull, a01 = 0ull, a10 = 0ull, a11 = 0ull;

        if (s > 0) {
            const float* hprev = out + (size_t)(s - 1) * (BB * HH);

            float hr[8], ur[4];
            // prologue: chunk 0 -> regs -> smem buf 0
#pragma unroll
            for (int j = 0; j < 8; j++)
                hr[j] = __ldcs(hprev + (8 * w + j) * HH + lane);
#pragma unroll
            for (int i = 0; i < 4; i++) {
                int c = w * 4 + i;
                int n = (c >> 3) * HH + j0 + (c & 7);
                ur[i] = Uw[(size_t)n * HH + lane];
            }
#pragma unroll
            for (int j = 0; j < 4; j++)
                *(ulonglong2*)&sh_h[hst + 2 * j] =
                    make_ulonglong2(dup2(hr[2 * j]), dup2(hr[2 * j + 1]));
            *(float4*)&sh_u[ust] = make_float4(ur[0], ur[1], ur[2], ur[3]);

            int buf = 0;
            const int NCH = HH / KC;  // 32
            for (int ch = 0; ch < NCH; ch++) {
                __syncthreads();  // buf[buf] ready
                if (ch + 1 < NCH) {
                    int kc = (ch + 1) * KC;
#pragma unroll
                    for (int j = 0; j < 8; j++)
                        hr[j] = __ldcs(hprev + (8 * w + j) * HH + kc + lane);
#pragma unroll
                    for (int i = 0; i < 4; i++) {
                        int c = w * 4 + i;
                        int n = (c >> 3) * HH + j0 + (c & 7);
                        ur[i] = Uw[(size_t)n * HH + kc + lane];
                    }
                }
                const unsigned long long* hb = sh_h + buf * (KC * 66) + m0;
                const float* ub = sh_u + buf * (KC * 36) + n0;
#pragma unroll
                for (int kk = 0; kk < KC; kk++) {
                    ulonglong2 hp = *(const ulonglong2*)(hb + kk * 66);
                    ulonglong2 up = *(const ulonglong2*)(ub + kk * 36);
                    a00 = fma2(hp.x, up.x, a00);
                    a01 = fma2(hp.x, up.y, a01);
                    a10 = fma2(hp.y, up.x, a10);
                    a11 = fma2(hp.y, up.y, a11);
                }
                if (ch + 1 < NCH) {
                    int nb = buf ^ 1;
#pragma unroll
                    for (int j = 0; j < 4; j++)
                        *(ulonglong2*)&sh_h[nb * (KC * 66) + hst + 2 * j] =
                            make_ulonglong2(dup2(hr[2 * j]), dup2(hr[2 * j + 1]));
                    *(float4*)&sh_u[nb * (KC * 36) + ust] =
                        make_float4(ur[0], ur[1], ur[2], ur[3]);
                }
                buf ^= 1;
            }
        }
        __syncthreads();  // everyone done reading sh_u before gbuf reuse

        // gate exchange: acc -> smem (rows m0,m0+1; cols n0..n0+3)
        *(unsigned long long*)&gb[m0 * 34 + n0]           = a00;
        *(unsigned long long*)&gb[m0 * 34 + n0 + 2]       = a01;
        *(unsigned long long*)&gb[(m0 + 1) * 34 + n0]     = a10;
        *(unsigned long long*)&gb[(m0 + 1) * 34 + n0 + 2] = a11;
        __syncthreads();

        // fused pointwise LSTM update: 512 (b, unit) pairs, 2 per thread
        const int t = s >> 1;
        const size_t gbase = (size_t)(t * BB) * G4;
#pragma unroll
        for (int e = 0; e < 2; e++) {
            int p = tid * 2 + e;
            int b = p >> 3, uu = p & 7;
            size_t gg_idx = gbase + (size_t)b * G4 + j0 + uu;
            float gi = gb[b * 34 + uu]      + __ldcs(&g_G[gg_idx]);
            float gf = gb[b * 34 + 8 + uu]  + __ldcs(&g_G[gg_idx + HH]);
            float gG = gb[b * 34 + 16 + uu] + __ldcs(&g_G[gg_idx + 2 * HH]);
            float go = gb[b * 34 + 24 + uu] + __ldcs(&g_G[gg_idx + 3 * HH]);

            size_t oidx = (size_t)s * (BB * HH) + (size_t)b * HH + j0 + uu;
            float cp = 0.f;
            if (s > 0)
                cp = __ldcs(&out[(size_t)NSTEP * (BB * HH) + oidx - (BB * HH)]);
            float cn = cp * sigm(gf) + sigm(gi) * tanhf(gG);
            float hn = sigm(go) * tanhf(cn);
            out[oidx] = hn;
            out[(size_t)NSTEP * (BB * HH) + oidx] = cn;
        }

        grid_barrier(tid);  // h/c of step s visible chip-wide before step s+1
    }
}

// ---------------------------------------------------------------------------
// Precompute kernel: G[t][b][n] = bias[n] + sum_k x[b][t][k] * Ww[n][k]
// Grid: (128 n-groups of 32, 512 t). Same micro-kernel + staging fix, K = 512.
// ---------------------------------------------------------------------------
__global__ __launch_bounds__(256, 1) void lstm_pre(const float* __restrict__ x,
                                                   const float* __restrict__ Ww,
                                                   const float* __restrict__ bw,
                                                   const float* __restrict__ bu) {
    __shared__ __align__(16) unsigned long long sh_h[2 * KC * 66];
    __shared__ __align__(16) float sh_u[2 * KC * 36];
    float* gb = sh_u;

    const int tid  = threadIdx.x;
    const int lane = tid & 31;
    const int w    = tid >> 5;
    const int n0g  = blockIdx.x * 32;
    const int t    = blockIdx.y;
    const int mg   = tid >> 3, ng = tid & 7;
    const int m0   = mg * 2,  n0 = ng * 4;

    const int hst = lane * 66 + 8 * w;
    const int ust = lane * 36 + 4 * w;

    unsigned long long a00 = 0ull, a01 = 0ull, a10 = 0ull, a11 = 0ull;

    float hr[8], ur[4];
#pragma unroll
    for (int j = 0; j < 8; j++)
        hr[j] = __ldcs(&x[((size_t)(8 * w + j) * TTT + t) * IN + lane]);
#pragma unroll
    for (int i = 0; i < 4; i++)
        ur[i] = Ww[(size_t)(n0g + w * 4 + i) * IN + lane];
#pragma unroll
    for (int j = 0; j < 4; j++)
        *(ulonglong2*)&sh_h[hst + 2 * j] =
            make_ulonglong2(dup2(hr[2 * j]), dup2(hr[2 * j + 1]));
    *(float4*)&sh_u[ust] = make_float4(ur[0], ur[1], ur[2], ur[3]);

    int buf = 0;
    const int NCH = IN / KC;  // 16
    for (int ch = 0; ch < NCH; ch++) {
        __syncthreads();
        if (ch + 1 < NCH) {
            int kc = (ch + 1) * KC;
#pragma unroll
            for (int j = 0; j < 8; j++)
                hr[j] = __ldcs(&x[((size_t)(8 * w + j) * TTT + t) * IN + kc + lane]);
#pragma unroll
            for (int i = 0; i < 4; i++)
                ur[i] = Ww[(size_t)(n0g + w * 4 + i) * IN + kc + lane];
        }
        const unsigned long long* hb = sh_h + buf * (KC * 66) + m0;
        const float* ub = sh_u + buf * (KC * 36) + n0;
#pragma unroll
        for (int kk = 0; kk < KC; kk++) {
            ulonglong2 hp = *(const ulonglong2*)(hb + kk * 66);
            ulonglong2 up = *(const ulonglong2*)(ub + kk * 36);
            a00 = fma2(hp.x, up.x, a00);
            a01 = fma2(hp.x, up.y, a01);
            a10 = fma2(hp.y, up.x, a10);
            a11 = fma2(hp.y, up.y, a11);
        }
        if (ch + 1 < NCH) {
            int nb = buf ^ 1;
#pragma unroll
            for (int j = 0; j < 4; j++)
                *(ulonglong2*)&sh_h[nb * (KC * 66) + hst + 2 * j] =
                    make_ulonglong2(dup2(hr[2 * j]), dup2(hr[2 * j + 1]));
            *(float4*)&sh_u[nb * (KC * 36) + ust] =
                make_float4(ur[0], ur[1], ur[2], ur[3]);
        }
        buf ^= 1;
    }
    __syncthreads();

    *(unsigned long long*)&gb[m0 * 34 + n0]           = a00;
    *(unsigned long long*)&gb[m0 * 34 + n0 + 2]       = a01;
    *(unsigned long long*)&gb[(m0 + 1) * 34 + n0]     = a10;
    *(unsigned long long*)&gb[(m0 + 1) * 34 + n0 + 2] = a11;
    __syncthreads();

    // coalesced flush + bias
#pragma unroll
    for (int i = 0; i < 8; i++) {
        int f = i * 256 + tid;
        int b = f >> 5, c = f & 31;
        int n = n0g + c;
        g_G[((size_t)t * BB + b) * G4 + n] = gb[b * 34 + c] + bw[n] + bu[n];
    }
}

extern "C" void kernel_launch(void* const* d_in, const int* in_sizes, int n_in,
                              void* d_out, int out_size) {
    const float* x  = (const float*)d_in[0];
    const float* Ww = (const float*)d_in[1];
    const float* bw = (const float*)d_in[2];
    const float* Uw = (const float*)d_in[3];
    const float* bu = (const float*)d_in[4];
    float* out = (float*)d_out;

    (void)in_sizes; (void)n_in; (void)out_size;

    lstm_pre<<<dim3(128, 512), 256>>>(x, Ww, bw, bu);
    lstm_scan<<<NCTA, 256>>>(Uw, out);
}

// round 12
// speedup vs baseline: 2.8599x; 1.8051x over previous
#include <cuda_runtime.h>

#define BB    64
#define TTT   512
#define IN    512
#define HH    1024
#define G4    4096
#define NSTEP 1024
#define KC    32
#define NCTA  128
#define SH    68   // sh_h row stride (floats), ==4 mod 32, 16B-aligned rows
#define SU    36   // sh_u row stride (floats), ==4 mod 32

// 512 MB scratch for G[t][b][4096] = x_t @ Ww^T + (bw + bu)
__device__ float g_G[(size_t)TTT * BB * G4];

// grid-barrier state
__device__ unsigned g_cnt;
__device__ volatile unsigned g_gen;

__device__ __forceinline__ unsigned long long fma2(unsigned long long a,
                                                   unsigned long long b,
                                                   unsigned long long c) {
    unsigned long long d;
    asm("fma.rn.f32x2 %0, %1, %2, %3;" : "=l"(d) : "l"(a), "l"(b), "l"(c));
    return d;
}
__device__ __forceinline__ unsigned long long addf2(unsigned long long a,
                                                    unsigned long long b) {
    unsigned long long d;
    asm("add.rn.f32x2 %0, %1, %2;" : "=l"(d) : "l"(a), "l"(b));
    return d;
}
__device__ __forceinline__ unsigned long long dup2(float v) {
    unsigned int u = __float_as_uint(v);
    unsigned long long d;
    asm("mov.b64 %0, {%1, %1};" : "=l"(d) : "r"(u));
    return d;
}
__device__ __forceinline__ unsigned long long pack2(float a, float b) {
    unsigned long long d;
    asm("mov.b64 %0, {%1, %2};" : "=l"(d)
        : "r"(__float_as_uint(a)), "r"(__float_as_uint(b)));
    return d;
}
__device__ __forceinline__ float sigm(float x) { return 1.f / (1.f + __expf(-x)); }

__device__ __forceinline__ void grid_barrier(int tid) {
    __syncthreads();
    if (tid == 0) {
        __threadfence();
        unsigned gen = g_gen;
        if (atomicAdd(&g_cnt, 1u) == NCTA - 1) {
            g_cnt = 0;
            __threadfence();
            g_gen = gen + 1;
        } else {
            while (g_gen == gen) { }
        }
        __threadfence();
    }
    __syncthreads();
}

// ---------------------------------------------------------------------------
// Persistent scan: 128 CTAs (1/SM), s = 0..1023.
// GEMM: gates = h_prev @ Uw^T, CTA tile 64x32, K=1024 (KC=32 double-buffered).
// Micro-kernel: 256 thr = 32 positions (8Mx8N tile) x 8 k-slices.
// Per thread per k: 2 LDS.128 h (plain) + 2 LDS.128 u (f32x2 pairs),
// 32 fma.rn.f32x2 -> 1 B smem per FMA; LDS floor == FMA floor == 16 cyc/k/SM.
// K-slice partials combined by shfl reduce-scatter; fused LSTM pointwise.
// ---------------------------------------------------------------------------
__global__ __launch_bounds__(256, 1) void lstm_scan(const float* __restrict__ Uw,
                                                    float* __restrict__ out) {
    __shared__ __align__(16) float sh_h[2 * KC * SH];
    __shared__ __align__(16) float sh_u[2 * KC * SU];
    float* gb = sh_u;  // gate-exchange buffer (64 x 34 floats) aliases sh_u

    const int tid  = threadIdx.x;
    const int lane = tid & 31;
    const int w    = tid >> 5;
    const int g    = blockIdx.x;
    const int j0   = g * 8;
    const int pos  = tid >> 3;          // 0..31
    const int ks   = tid & 7;           // k-slice
    const int m0   = (pos >> 2) * 8;    // = 8*w within a warp
    const int n0   = (pos & 3) * 8;

    const int hst = lane * SH + 8 * w;  // staging: row k=lane, cols 8w..8w+7
    const int ust = lane * SU + 4 * w;  // staging: row k=lane, cols 4w..4w+3

    size_t uoff[4];                     // Uw offsets for staged columns
#pragma unroll
    for (int i = 0; i < 4; i++) {
        int c = 4 * w + i;
        int n = (c >> 3) * HH + j0 + (c & 7);
        uoff[i] = (size_t)n * HH + lane;
    }

    const int pb0 = (2 * tid) >> 3,     pu0 = (2 * tid) & 7;
    const int pb1 = (2 * tid + 1) >> 3, pu1 = (2 * tid + 1) & 7;

    for (int s = 0; s < NSTEP; s++) {
        // ---- hoisted pointwise operands (DRAM latency hidden behind GEMM) ----
        const int t = s >> 1;
        const size_t gbase = (size_t)(t * BB) * G4;
        float gp[8], cp0 = 0.f, cp1 = 0.f;
        {
            size_t e0 = gbase + (size_t)pb0 * G4 + j0 + pu0;
            size_t e1 = gbase + (size_t)pb1 * G4 + j0 + pu1;
#pragma unroll
            for (int q = 0; q < 4; q++) {
                gp[q]     = __ldcs(&g_G[e0 + (size_t)q * HH]);
                gp[4 + q] = __ldcs(&g_G[e1 + (size_t)q * HH]);
            }
            if (s > 0) {
                size_t cb = (size_t)NSTEP * (BB * HH) + (size_t)(s - 1) * (BB * HH);
                cp0 = __ldcs(&out[cb + (size_t)pb0 * HH + j0 + pu0]);
                cp1 = __ldcs(&out[cb + (size_t)pb1 * HH + j0 + pu1]);
            }
        }

        unsigned long long acc[8][4];
#pragma unroll
        for (int m = 0; m < 8; m++)
#pragma unroll
            for (int p = 0; p < 4; p++) acc[m][p] = 0ull;

        if (s > 0) {
            const float* hprev = out + (size_t)(s - 1) * (BB * HH);
            float hr[8], ur[4];
#pragma unroll
            for (int j = 0; j < 8; j++)
                hr[j] = __ldcs(hprev + (8 * w + j) * HH + lane);
#pragma unroll
            for (int i = 0; i < 4; i++) ur[i] = Uw[uoff[i]];
            *(float4*)&sh_h[hst]     = make_float4(hr[0], hr[1], hr[2], hr[3]);
            *(float4*)&sh_h[hst + 4] = make_float4(hr[4], hr[5], hr[6], hr[7]);
            *(float4*)&sh_u[ust]     = make_float4(ur[0], ur[1], ur[2], ur[3]);

            int buf = 0;
            for (int ch = 0; ch < HH / KC; ch++) {
                __syncthreads();
                if (ch + 1 < HH / KC) {
                    int kc = (ch + 1) * KC;
#pragma unroll
                    for (int j = 0; j < 8; j++)
                        hr[j] = __ldcs(hprev + (8 * w + j) * HH + kc + lane);
#pragma unroll
                    for (int i = 0; i < 4; i++) ur[i] = Uw[uoff[i] + kc];
                }
                const float* hb = sh_h + buf * (KC * SH) + ks * SH + m0;
                const float* ub = sh_u + buf * (KC * SU) + ks * SU + n0;
#pragma unroll
                for (int kkk = 0; kkk < 4; kkk++) {          // k = kkk*8 + ks
                    float4 h0 = *(const float4*)(hb + kkk * 8 * SH);
                    float4 h1 = *(const float4*)(hb + kkk * 8 * SH + 4);
                    ulonglong2 u0 = *(const ulonglong2*)(ub + kkk * 8 * SU);
                    ulonglong2 u1 = *(const ulonglong2*)(ub + kkk * 8 * SU + 4);
                    float hm[8] = {h0.x, h0.y, h0.z, h0.w, h1.x, h1.y, h1.z, h1.w};
#pragma unroll
                    for (int m = 0; m < 8; m++) {
                        unsigned long long hd = dup2(hm[m]);
                        acc[m][0] = fma2(hd, u0.x, acc[m][0]);
                        acc[m][1] = fma2(hd, u0.y, acc[m][1]);
                        acc[m][2] = fma2(hd, u1.x, acc[m][2]);
                        acc[m][3] = fma2(hd, u1.y, acc[m][3]);
                    }
                }
                if (ch + 1 < HH / KC) {
                    int nb = buf ^ 1;
                    *(float4*)&sh_h[nb * (KC * SH) + hst] =
                        make_float4(hr[0], hr[1], hr[2], hr[3]);
                    *(float4*)&sh_h[nb * (KC * SH) + hst + 4] =
                        make_float4(hr[4], hr[5], hr[6], hr[7]);
                    *(float4*)&sh_u[nb * (KC * SU) + ust] =
                        make_float4(ur[0], ur[1], ur[2], ur[3]);
                }
                buf ^= 1;
            }
        }

        // ---- reduce-scatter over the 8 k-slices; m==ks row lands in acc[0] ----
#pragma unroll
        for (int b = 0; b < 3; b++) {
            const int d = 1 << b;
            const bool hi = (ks >> b) & 1;
#pragma unroll
            for (int mm = 0; mm < 8; mm += 2 * d) {
#pragma unroll
                for (int p = 0; p < 4; p++) {
                    unsigned long long lo = acc[mm][p], hx = acc[mm + d][p];
                    unsigned long long keep = hi ? hx : lo;
                    unsigned long long send = hi ? lo : hx;
                    unsigned long long r = __shfl_xor_sync(0xffffffffu, send, d);
                    acc[mm][p] = addf2(keep, r);
                }
            }
        }

        __syncthreads();  // all LDS of sh_u done before gb overwrite
        {
            int row = m0 + ks;
#pragma unroll
            for (int p = 0; p < 4; p++)
                *(unsigned long long*)&gb[row * 34 + n0 + 2 * p] = acc[0][p];
        }
        __syncthreads();

        // ---- fused pointwise LSTM update ----
        {
            float gi = gb[pb0 * 34 + pu0]      + gp[0];
            float gf = gb[pb0 * 34 + 8 + pu0]  + gp[1];
            float gg = gb[pb0 * 34 + 16 + pu0] + gp[2];
            float go = gb[pb0 * 34 + 24 + pu0] + gp[3];
            float cn = cp0 * sigm(gf) + sigm(gi) * tanhf(gg);
            float hn = sigm(go) * tanhf(cn);
            size_t o0 = (size_t)s * (BB * HH) + (size_t)pb0 * HH + j0 + pu0;
            out[o0] = hn;
            out[(size_t)NSTEP * (BB * HH) + o0] = cn;

            gi = gb[pb1 * 34 + pu1]      + gp[4];
            gf = gb[pb1 * 34 + 8 + pu1]  + gp[5];
            gg = gb[pb1 * 34 + 16 + pu1] + gp[6];
            go = gb[pb1 * 34 + 24 + pu1] + gp[7];
            cn = cp1 * sigm(gf) + sigm(gi) * tanhf(gg);
            hn = sigm(go) * tanhf(cn);
            size_t o1 = (size_t)s * (BB * HH) + (size_t)pb1 * HH + j0 + pu1;
            out[o1] = hn;
            out[(size_t)NSTEP * (BB * HH) + o1] = cn;
        }

        grid_barrier(tid);
    }
}

// ---------------------------------------------------------------------------
// Precompute: G[t][b][n] = bias[n] + sum_k x[b][t][k] * Ww[n][k]
// Grid (128 n-groups of 32, 512 t); same micro-kernel, K = 512; direct store.
// ---------------------------------------------------------------------------
__global__ __launch_bounds__(256) void lstm_pre(const float* __restrict__ x,
                                                const float* __restrict__ Ww,
                                                const float* __restrict__ bw,
                                                const float* __restrict__ bu) {
    __shared__ __align__(16) float sh_h[2 * KC * SH];
    __shared__ __align__(16) float sh_u[2 * KC * SU];

    const int tid  = threadIdx.x;
    const int lane = tid & 31;
    const int w    = tid >> 5;
    const int n0g  = blockIdx.x * 32;
    const int t    = blockIdx.y;
    const int pos  = tid >> 3, ks = tid & 7;
    const int m0   = (pos >> 2) * 8, n0 = (pos & 3) * 8;

    const int hst = lane * SH + 8 * w;
    const int ust = lane * SU + 4 * w;

    unsigned long long biasp[4];
#pragma unroll
    for (int p = 0; p < 4; p++) {
        int n = n0g + n0 + 2 * p;
        biasp[p] = pack2(bw[n] + bu[n], bw[n + 1] + bu[n + 1]);
    }

    unsigned long long acc[8][4];
#pragma unroll
    for (int m = 0; m < 8; m++)
#pragma unroll
        for (int p = 0; p < 4; p++) acc[m][p] = 0ull;

    float hr[8], ur[4];
#pragma unroll
    for (int j = 0; j < 8; j++)
        hr[j] = __ldcs(&x[((size_t)(8 * w + j) * TTT + t) * IN + lane]);
#pragma unroll
    for (int i = 0; i < 4; i++)
        ur[i] = Ww[(size_t)(n0g + 4 * w + i) * IN + lane];
    *(float4*)&sh_h[hst]     = make_float4(hr[0], hr[1], hr[2], hr[3]);
    *(float4*)&sh_h[hst + 4] = make_float4(hr[4], hr[5], hr[6], hr[7]);
    *(float4*)&sh_u[ust]     = make_float4(ur[0], ur[1], ur[2], ur[3]);

    int buf = 0;
    for (int ch = 0; ch < IN / KC; ch++) {
        __syncthreads();
        if (ch + 1 < IN / KC) {
            int kc = (ch + 1) * KC;
#pragma unroll
            for (int j = 0; j < 8; j++)
                hr[j] = __ldcs(&x[((size_t)(8 * w + j) * TTT + t) * IN + kc + lane]);
#pragma unroll
            for (int i = 0; i < 4; i++)
                ur[i] = Ww[(size_t)(n0g + 4 * w + i) * IN + kc + lane];
        }
        const float* hb = sh_h + buf * (KC * SH) + ks * SH + m0;
        const float* ub = sh_u + buf * (KC * SU) + ks * SU + n0;
#pragma unroll
        for (int kkk = 0; kkk < 4; kkk++) {
            float4 h0 = *(const float4*)(hb + kkk * 8 * SH);
            float4 h1 = *(const float4*)(hb + kkk * 8 * SH + 4);
            ulonglong2 u0 = *(const ulonglong2*)(ub + kkk * 8 * SU);
            ulonglong2 u1 = *(const ulonglong2*)(ub + kkk * 8 * SU + 4);
            float hm[8] = {h0.x, h0.y, h0.z, h0.w, h1.x, h1.y, h1.z, h1.w};
#pragma unroll
            for (int m = 0; m < 8; m++) {
                unsigned long long hd = dup2(hm[m]);
                acc[m][0] = fma2(hd, u0.x, acc[m][0]);
                acc[m][1] = fma2(hd, u0.y, acc[m][1]);
                acc[m][2] = fma2(hd, u1.x, acc[m][2]);
                acc[m][3] = fma2(hd, u1.y, acc[m][3]);
            }
        }
        if (ch + 1 < IN / KC) {
            int nb = buf ^ 1;
            *(float4*)&sh_h[nb * (KC * SH) + hst] =
                make_float4(hr[0], hr[1], hr[2], hr[3]);
            *(float4*)&sh_h[nb * (KC * SH) + hst + 4] =
                make_float4(hr[4], hr[5], hr[6], hr[7]);
            *(float4*)&sh_u[nb * (KC * SU) + ust] =
                make_float4(ur[0], ur[1], ur[2], ur[3]);
        }
        buf ^= 1;
    }

    // reduce-scatter over k-slices; final row (b = m0+ks) in acc[0]
#pragma unroll
    for (int b = 0; b < 3; b++) {
        const int d = 1 << b;
        const bool hi = (ks >> b) & 1;
#pragma unroll
        for (int mm = 0; mm < 8; mm += 2 * d) {
#pragma unroll
            for (int p = 0; p < 4; p++) {
                unsigned long long lo = acc[mm][p], hx = acc[mm + d][p];
                unsigned long long keep = hi ? hx : lo;
                unsigned long long send = hi ? lo : hx;
                unsigned long long r = __shfl_xor_sync(0xffffffffu, send, d);
                acc[mm][p] = addf2(keep, r);
            }
        }
    }

    {
        int row = m0 + ks;  // batch b
        size_t ob = ((size_t)t * BB + row) * G4 + n0g + n0;
#pragma unroll
        for (int p = 0; p < 4; p++)
            *(unsigned long long*)&g_G[ob + 2 * p] = addf2(acc[0][p], biasp[p]);
    }
}

extern "C" void kernel_launch(void* const* d_in, const int* in_sizes, int n_in,
                              void* d_out, int out_size) {
    const float* x  = (const float*)d_in[0];
    const float* Ww = (const float*)d_in[1];
    const float* bw = (const float*)d_in[2];
    const float* Uw = (const float*)d_in[3];
    const float* bu = (const float*)d_in[4];
    float* out = (float*)d_out;

    (void)in_sizes; (void)n_in; (void)out_size;

    lstm_pre<<<dim3(128, 512), 256>>>(x, Ww, bw, bu);
    lstm_scan<<<NCTA, 256>>>(Uw, out);
}

// round 13
// speedup vs baseline: 3.1461x; 1.1001x over previous
#include <cuda_runtime.h>

#define BB    64
#define TTT   512
#define IN    512
#define HH    1024
#define G4    4096
#define NSTEP 1024
#define KC    32
#define NCTA  128
#define SH    66   // sh_h row stride (floats): 4*SH==8 mod 128 -> 16 slices spread banks
#define SU    34   // sh_u row stride (floats): same property

// 512 MB scratch for G[t][b][4096] = x_t @ Ww^T + (bw + bu)
__device__ float g_G[(size_t)TTT * BB * G4];

// grid-barrier state
__device__ unsigned g_cnt;
__device__ volatile unsigned g_gen;

__device__ __forceinline__ unsigned long long fma2(unsigned long long a,
                                                   unsigned long long b,
                                                   unsigned long long c) {
    unsigned long long d;
    asm("fma.rn.f32x2 %0, %1, %2, %3;" : "=l"(d) : "l"(a), "l"(b), "l"(c));
    return d;
}
__device__ __forceinline__ unsigned long long addf2(unsigned long long a,
                                                    unsigned long long b) {
    unsigned long long d;
    asm("add.rn.f32x2 %0, %1, %2;" : "=l"(d) : "l"(a), "l"(b));
    return d;
}
__device__ __forceinline__ unsigned long long dup2(float v) {
    unsigned int u = __float_as_uint(v);
    unsigned long long d;
    asm("mov.b64 %0, {%1, %1};" : "=l"(d) : "r"(u));
    return d;
}
__device__ __forceinline__ unsigned long long pack2(float a, float b) {
    unsigned long long d;
    asm("mov.b64 %0, {%1, %2};" : "=l"(d)
        : "r"(__float_as_uint(a)), "r"(__float_as_uint(b)));
    return d;
}
__device__ __forceinline__ float lo2(unsigned long long v) {
    return __uint_as_float((unsigned)v);
}
__device__ __forceinline__ float hi2(unsigned long long v) {
    return __uint_as_float((unsigned)(v >> 32));
}
__device__ __forceinline__ float sigm(float x) { return 1.f / (1.f + __expf(-x)); }

__device__ __forceinline__ void grid_barrier(int tid) {
    __syncthreads();
    if (tid == 0) {
        __threadfence();
        unsigned gen = g_gen;
        if (atomicAdd(&g_cnt, 1u) == NCTA - 1) {
            g_cnt = 0;
            __threadfence();
            g_gen = gen + 1;
        } else {
            while (g_gen == gen) { }
        }
        __threadfence();
    }
    __syncthreads();
}

// core GEMM micro-body: one k value (LDS.64 x8, 8 dup, 32 fma2)
#define MICRO_K(hq, uq, acc)                                                   \
    do {                                                                       \
        unsigned long long up0 = *(const unsigned long long*)((uq) + 0);       \
        unsigned long long up1 = *(const unsigned long long*)((uq) + 2);       \
        unsigned long long up2 = *(const unsigned long long*)((uq) + 4);       \
        unsigned long long up3 = *(const unsigned long long*)((uq) + 6);       \
        _Pragma("unroll")                                                      \
        for (int j = 0; j < 4; j++) {                                          \
            unsigned long long hp = *(const unsigned long long*)((hq) + 2 * j);\
            unsigned long long d0 = dup2(lo2(hp));                             \
            unsigned long long d1 = dup2(hi2(hp));                             \
            acc[2 * j][0]     = fma2(d0, up0, acc[2 * j][0]);                  \
            acc[2 * j][1]     = fma2(d0, up1, acc[2 * j][1]);                  \
            acc[2 * j][2]     = fma2(d0, up2, acc[2 * j][2]);                  \
            acc[2 * j][3]     = fma2(d0, up3, acc[2 * j][3]);                  \
            acc[2 * j + 1][0] = fma2(d1, up0, acc[2 * j + 1][0]);              \
            acc[2 * j + 1][1] = fma2(d1, up1, acc[2 * j + 1][1]);              \
            acc[2 * j + 1][2] = fma2(d1, up2, acc[2 * j + 1][2]);              \
            acc[2 * j + 1][3] = fma2(d1, up3, acc[2 * j + 1][3]);              \
        }                                                                      \
    } while (0)

// reduce-scatter over 16 k-slices: 3 m-stages + 1 p-stage.
// result: res0/res1 = row (m0 + (ks&7)), cols n0 + 4*(ks>>3) .. +3
#define REDUCE_SCATTER(acc, ks, res0, res1)                                    \
    do {                                                                       \
        _Pragma("unroll")                                                      \
        for (int b = 0; b < 3; b++) {                                          \
            const int d = 1 << b;                                              \
            const bool hi = ((ks) >> b) & 1;                                   \
            _Pragma("unroll")                                                  \
            for (int mm = 0; mm < 8; mm += 2 * d) {                            \
                _Pragma("unroll")                                              \
                for (int p = 0; p < 4; p++) {                                  \
                    unsigned long long L = acc[mm][p], H = acc[mm + d][p];     \
                    unsigned long long keep = hi ? H : L;                      \
                    unsigned long long send = hi ? L : H;                      \
                    unsigned long long r = __shfl_xor_sync(0xffffffffu, send, d);\
                    acc[mm][p] = addf2(keep, r);                               \
                }                                                              \
            }                                                                  \
        }                                                                      \
        {                                                                      \
            const bool hi = ((ks) >> 3) & 1;                                   \
            unsigned long long k0 = hi ? acc[0][2] : acc[0][0];                \
            unsigned long long k1 = hi ? acc[0][3] : acc[0][1];                \
            unsigned long long s0 = hi ? acc[0][0] : acc[0][2];                \
            unsigned long long s1 = hi ? acc[0][1] : acc[0][3];                \
            unsigned long long r0 = __shfl_xor_sync(0xffffffffu, s0, 8);       \
            unsigned long long r1 = __shfl_xor_sync(0xffffffffu, s1, 8);       \
            res0 = addf2(k0, r0);                                              \
            res1 = addf2(k1, r1);                                              \
        }                                                                      \
    } while (0)

// ---------------------------------------------------------------------------
// Persistent scan: 128 CTAs x 512 threads (16 warps/SM), s = 0..1023.
// CTA tile 64x32, K=1024 (KC=32 double-buffered).
// 512 thr = 32 positions (8Mx8N) x 16 k-slices; inner loads LDS.64 only,
// strides SH=66 / SU=34 give conflict-free 16-slice bank spread.
// ---------------------------------------------------------------------------
__global__ __launch_bounds__(512, 1) void lstm_scan(const float* __restrict__ Uw,
                                                    float* __restrict__ out) {
    __shared__ __align__(16) float sh_h[2 * KC * SH];
    __shared__ __align__(16) float sh_u[2 * KC * SU];
    float* gb = sh_u;  // gate-exchange buffer (64 x 34) aliases sh_u exactly

    const int tid  = threadIdx.x;
    const int krow = tid & 31;          // staging k row
    const int a    = tid >> 5;          // staging group 0..15
    const int pos  = tid >> 4;          // 0..31
    const int ks   = tid & 15;          // k-slice
    const int m0   = (pos >> 2) * 8;
    const int n0   = (pos & 3) * 8;
    const int g    = blockIdx.x;
    const int j0   = g * 8;

    size_t uoff[2];
#pragma unroll
    for (int i = 0; i < 2; i++) {
        int c = 2 * a + i;
        int n = (c >> 3) * HH + j0 + (c & 7);
        uoff[i] = (size_t)n * HH + krow;
    }

    const int pb = tid >> 3, pu = tid & 7;   // pointwise (batch, unit)

    for (int s = 0; s < NSTEP; s++) {
        // hoisted pointwise operands
        const int t = s >> 1;
        const size_t gbase = (size_t)(t * BB) * G4;
        float gp[4], cp = 0.f;
        {
            size_t e0 = gbase + (size_t)pb * G4 + j0 + pu;
#pragma unroll
            for (int q = 0; q < 4; q++) gp[q] = __ldcs(&g_G[e0 + (size_t)q * HH]);
            if (s > 0)
                cp = __ldcs(&out[(size_t)NSTEP * (BB * HH) +
                                 (size_t)(s - 1) * (BB * HH) +
                                 (size_t)pb * HH + j0 + pu]);
        }

        unsigned long long acc[8][4];
#pragma unroll
        for (int m = 0; m < 8; m++)
#pragma unroll
            for (int p = 0; p < 4; p++) acc[m][p] = 0ull;

        if (s > 0) {
            const float* hprev = out + (size_t)(s - 1) * (BB * HH);
            float hr[4], ur[2];
#pragma unroll
            for (int j = 0; j < 4; j++)
                hr[j] = __ldcs(hprev + (4 * a + j) * HH + krow);
#pragma unroll
            for (int i = 0; i < 2; i++) ur[i] = Uw[uoff[i]];
            *(float2*)&sh_h[krow * SH + 4 * a]     = make_float2(hr[0], hr[1]);
            *(float2*)&sh_h[krow * SH + 4 * a + 2] = make_float2(hr[2], hr[3]);
            *(float2*)&sh_u[krow * SU + 2 * a]     = make_float2(ur[0], ur[1]);

            int buf = 0;
            for (int ch = 0; ch < HH / KC; ch++) {
                __syncthreads();
                if (ch + 1 < HH / KC) {
                    int kc = (ch + 1) * KC;
#pragma unroll
                    for (int j = 0; j < 4; j++)
                        hr[j] = __ldcs(hprev + (4 * a + j) * HH + kc + krow);
#pragma unroll
                    for (int i = 0; i < 2; i++) ur[i] = Uw[uoff[i] + kc];
                }
                const float* hb = sh_h + buf * (KC * SH) + ks * SH + m0;
                const float* ub = sh_u + buf * (KC * SU) + ks * SU + n0;
                MICRO_K(hb, ub, acc);
                MICRO_K(hb + 16 * SH, ub + 16 * SU, acc);
                if (ch + 1 < HH / KC) {
                    int nb = buf ^ 1;
                    *(float2*)&sh_h[nb * (KC * SH) + krow * SH + 4 * a] =
                        make_float2(hr[0], hr[1]);
                    *(float2*)&sh_h[nb * (KC * SH) + krow * SH + 4 * a + 2] =
                        make_float2(hr[2], hr[3]);
                    *(float2*)&sh_u[nb * (KC * SU) + krow * SU + 2 * a] =
                        make_float2(ur[0], ur[1]);
                }
                buf ^= 1;
            }
        }

        unsigned long long res0, res1;
        REDUCE_SCATTER(acc, ks, res0, res1);

        __syncthreads();  // all LDS of sh_u done before gb overwrite
        {
            int row = m0 + (ks & 7);
            int cb  = n0 + 4 * ((ks >> 3) & 1);
            *(unsigned long long*)&gb[row * SU + cb]     = res0;
            *(unsigned long long*)&gb[row * SU + cb + 2] = res1;
        }
        __syncthreads();

        // fused pointwise LSTM update (one (b,unit) per thread)
        {
            float gi = gb[pb * SU + pu]      + gp[0];
            float gf = gb[pb * SU + 8 + pu]  + gp[1];
            float gg = gb[pb * SU + 16 + pu] + gp[2];
            float go = gb[pb * SU + 24 + pu] + gp[3];
            float cn = cp * sigm(gf) + sigm(gi) * tanhf(gg);
            float hn = sigm(go) * tanhf(cn);
            size_t o = (size_t)s * (BB * HH) + (size_t)pb * HH + j0 + pu;
            out[o] = hn;
            out[(size_t)NSTEP * (BB * HH) + o] = cn;
        }

        grid_barrier(tid);
    }
}

// ---------------------------------------------------------------------------
// Precompute: G[t][b][n] = bias[n] + sum_k x[b][t][k] * Ww[n][k]
// Grid (128 n-groups of 32, 512 t) x 512 threads; K = 512; direct store.
// ---------------------------------------------------------------------------
__global__ __launch_bounds__(512, 1) void lstm_pre(const float* __restrict__ x,
                                                   const float* __restrict__ Ww,
                                                   const float* __restrict__ bw,
                                                   const float* __restrict__ bu) {
    __shared__ __align__(16) float sh_h[2 * KC * SH];
    __shared__ __align__(16) float sh_u[2 * KC * SU];

    const int tid  = threadIdx.x;
    const int krow = tid & 31;
    const int a    = tid >> 5;
    const int pos  = tid >> 4;
    const int ks   = tid & 15;
    const int m0   = (pos >> 2) * 8;
    const int n0   = (pos & 3) * 8;
    const int n0g  = blockIdx.x * 32;
    const int t    = blockIdx.y;

    unsigned long long acc[8][4];
#pragma unroll
    for (int m = 0; m < 8; m++)
#pragma unroll
        for (int p = 0; p < 4; p++) acc[m][p] = 0ull;

    float hr[4], ur[2];
#pragma unroll
    for (int j = 0; j < 4; j++)
        hr[j] = __ldcs(&x[((size_t)(4 * a + j) * TTT + t) * IN + krow]);
#pragma unroll
    for (int i = 0; i < 2; i++)
        ur[i] = Ww[(size_t)(n0g + 2 * a + i) * IN + krow];
    *(float2*)&sh_h[krow * SH + 4 * a]     = make_float2(hr[0], hr[1]);
    *(float2*)&sh_h[krow * SH + 4 * a + 2] = make_float2(hr[2], hr[3]);
    *(float2*)&sh_u[krow * SU + 2 * a]     = make_float2(ur[0], ur[1]);

    int buf = 0;
    for (int ch = 0; ch < IN / KC; ch++) {
        __syncthreads();
        if (ch + 1 < IN / KC) {
            int kc = (ch + 1) * KC;
#pragma unroll
            for (int j = 0; j < 4; j++)
                hr[j] = __ldcs(&x[((size_t)(4 * a + j) * TTT + t) * IN + kc + krow]);
#pragma unroll
            for (int i = 0; i < 2; i++)
                ur[i] = Ww[(size_t)(n0g + 2 * a + i) * IN + kc + krow];
        }
        const float* hb = sh_h + buf * (KC * SH) + ks * SH + m0;
        const float* ub = sh_u + buf * (KC * SU) + ks * SU + n0;
        MICRO_K(hb, ub, acc);
        MICRO_K(hb + 16 * SH, ub + 16 * SU, acc);
        if (ch + 1 < IN / KC) {
            int nb = buf ^ 1;
            *(float2*)&sh_h[nb * (KC * SH) + krow * SH + 4 * a] =
                make_float2(hr[0], hr[1]);
            *(float2*)&sh_h[nb * (KC * SH) + krow * SH + 4 * a + 2] =
                make_float2(hr[2], hr[3]);
            *(float2*)&sh_u[nb * (KC * SU) + krow * SU + 2 * a] =
                make_float2(ur[0], ur[1]);
        }
        buf ^= 1;
    }

    unsigned long long res0, res1;
    REDUCE_SCATTER(acc, ks, res0, res1);

    {
        int row = m0 + (ks & 7);                  // batch b
        int cb  = n0 + 4 * ((ks >> 3) & 1);       // local col base
        int n   = n0g + cb;
        unsigned long long b01 = pack2(bw[n] + bu[n], bw[n + 1] + bu[n + 1]);
        unsigned long long b23 = pack2(bw[n + 2] + bu[n + 2], bw[n + 3] + bu[n + 3]);
        size_t ob = ((size_t)t * BB + row) * G4 + n;
        *(unsigned long long*)&g_G[ob]     = addf2(res0, b01);
        *(unsigned long long*)&g_G[ob + 2] = addf2(res1, b23);
    }
}

extern "C" void kernel_launch(void* const* d_in, const int* in_sizes, int n_in,
                              void* d_out, int out_size) {
    const float* x  = (const float*)d_in[0];
    const float* Ww = (const float*)d_in[1];
    const float* bw = (const float*)d_in[2];
    const float* Uw = (const float*)d_in[3];
    const float* bu = (const float*)d_in[4];
    float* out = (float*)d_out;

    (void)in_sizes; (void)n_in; (void)out_size;

    lstm_pre<<<dim3(128, 512), 512>>>(x, Ww, bw, bu);
    lstm_scan<<<NCTA, 512>>>(Uw, out);
}